// round 15
// baseline (speedup 1.0000x reference)
#include <cuda_runtime.h>
#include <math.h>
#include <stdint.h>

#define CC    256
#define GG    4
#define NB    2
#define OMC   108          // G*K*3
#define TP    5376         // total pixels per batch across scales (4096+1024+256)
#define SEL3(s,a,b,c) ((s)==0 ? (a) : ((s)==1 ? (b) : (c)))

typedef unsigned long long ull;

__device__ __forceinline__ ull f2pk(float lo, float hi) {
    ull r; asm("mov.b64 %0, {%1, %2};" : "=l"(r) : "f"(lo), "f"(hi)); return r;
}
__device__ __forceinline__ void f2fma(ull &d, ull a, ull b) {
    asm("fma.rn.f32x2 %0, %1, %2, %0;" : "+l"(d) : "l"(a), "l"(b));
}
__device__ __forceinline__ float2 f2up(ull v) {
    float2 o; asm("mov.b64 {%0, %1}, %2;" : "=f"(o.x), "=f"(o.y) : "l"(v)); return o;
}
__device__ __forceinline__ float tf32r(float x) {
    float r; asm("cvt.rna.tf32.f32 %0, %1;" : "=f"(r) : "f"(x)); return r;
}

// warp-level tf32 MMA (sm_80+ path; compiles on plain sm_103)
#define MMA8(d, a, b0, b1) \
    asm volatile("mma.sync.aligned.m16n8k8.row.col.f32.tf32.tf32.f32 " \
        "{%0,%1,%2,%3}, {%4,%5,%6,%7}, {%8,%9}, {%0,%1,%2,%3};" \
        : "+f"((d)[0]), "+f"((d)[1]), "+f"((d)[2]), "+f"((d)[3]) \
        : "r"((a)[0]), "r"((a)[1]), "r"((a)[2]), "r"((a)[3]), "r"(b0), "r"(b1))

// ---------------- scratch (static device globals) ---------------------------
__device__ float g_xt [NB*TP*CC];        // scaled input, pixel-major [b][p][c]
__device__ float g_om [NB*OMC*TP];       // offset/mask conv output (per-scale blocks)
__device__ float g_dcn[NB*TP*CC];
__device__ float g_d  [NB*TP*CC];
__device__ float g_x2t[NB*TP*CC];
__device__ float g_wt [72*32*112];       // conv weights tf32: [tap*8+ck][kk(32)][n(112)]
__device__ float g_wpj[CC*CC];           // proj weights tf32, transposed: [k][n]
__device__ ull   g_gpk[NB*GG*9*4*TP];    // packed {idx, weff} per (b,g,k,corner,pixel)
__device__ float g_pool [3*NB*CC];
__device__ float g_sfac [3*NB*CC];
__device__ float g_part [NB*84*CC];
__device__ float g_ab  [4*3*NB*CC];

#define OMOFF(s) SEL3(s, 0, 884736, 1105920)

// ---------------- merged prep: conv weights + proj transpose + pool ----------
__global__ __launch_bounds__(256) void k_prep(const float* __restrict__ wom,
                                              const float* __restrict__ wp,
                                              const float* __restrict__ f1,
                                              const float* __restrict__ f2,
                                              const float* __restrict__ f3) {
    int bx = blockIdx.x;
    if (bx < 1008) {
        int idx = bx*256 + threadIdx.x;
        int i = idx / 3584, r = idx % 3584, kk = r / 112, n = r % 112;
        int t = i >> 3, ck = i & 7, c = ck*32 + kk;
        float v = (n < OMC) ? wom[n*2304 + c*9 + t] : 0.f;
        g_wt[idx] = tf32r(v);
    } else if (bx < 1264) {
        int idx = (bx - 1008)*256 + threadIdx.x;   // < 65536
        int k = idx >> 8, n = idx & 255;
        g_wpj[idx] = tf32r(wp[n*CC + k]);
    } else {
        int pb = bx - 1264;                        // < 1536
        int c = pb & 255, b = (pb >> 8) & 1, s = pb >> 9;
        int HW = 4096 >> (2*s);
        const float* x = SEL3(s, f1, f2, f3);
        const float* p = x + ((size_t)b*CC + c)*HW;
        float v = 0.f;
        for (int i = threadIdx.x; i < HW; i += 256) v += p[i];
        __shared__ float sm[8];
        int lane = threadIdx.x & 31, wid = threadIdx.x >> 5;
#pragma unroll
        for (int o = 16; o; o >>= 1) v += __shfl_down_sync(0xffffffffu, v, o);
        if (!lane) sm[wid] = v;
        __syncthreads();
        if (threadIdx.x == 0) {
            float t = 0.f;
#pragma unroll
            for (int i = 0; i < 8; i++) t += sm[i];
            g_pool[(s*NB + b)*CC + c] = t / (float)HW;
        }
    }
}

__global__ __launch_bounds__(256) void k_scale_gemv(const float* __restrict__ wsc,
                                                    const float* __restrict__ bsc) {
    int gw = (blockIdx.x*blockDim.x + threadIdx.x) >> 5;
    int lane = threadIdx.x & 31;
    if (gw >= 3*NB*CC) return;
    int sb = gw / CC, o = gw % CC;
    const float* wr = wsc + (size_t)o*CC;
    const float* pr = g_pool + sb*CC;
    float v = 0.f;
#pragma unroll
    for (int i = 0; i < CC/32; i++) v = fmaf(wr[lane + i*32], pr[lane + i*32], v);
#pragma unroll
    for (int o2 = 16; o2; o2 >>= 1) v += __shfl_down_sync(0xffffffffu, v, o2);
    if (!lane) {
        v = (v + bsc[o] + 1.f) * 0.5f;
        g_sfac[sb*CC + o] = fminf(fmaxf(v, 0.f), 1.f);
    }
}

// scale + transpose to pixel-major (vectorized; x-tile cum {128,160,168})
__global__ __launch_bounds__(256) void k_apply(const float* __restrict__ f1,
                                               const float* __restrict__ f2,
                                               const float* __restrict__ f3) {
    __shared__ float sm[32*33];
    int bx = blockIdx.x;
    int s = (bx >= 128) + (bx >= 160);
    int base = SEL3(s, 0, 128, 160);
    int HW = 4096 >> (2*s);
    int SOFF = SEL3(s, 0, 4096, 5120);
    const float* x = SEL3(s, f1, f2, f3);
    int b = blockIdx.z;
    int hw0 = (bx - base)*32, c0 = blockIdx.y*32;
    int t = threadIdx.x;
    int cr = t >> 3, q = t & 7;
    float4 v = *(const float4*)(x + ((size_t)b*CC + c0 + cr)*HW + hw0 + q*4);
    float sf = g_sfac[(s*NB + b)*CC + c0 + cr];
    sm[cr*33 + q*4+0] = v.x*sf;
    sm[cr*33 + q*4+1] = v.y*sf;
    sm[cr*33 + q*4+2] = v.z*sf;
    sm[cr*33 + q*4+3] = v.w*sf;
    __syncthreads();
    // write: hh = cr, channel chunk q
    float4 o;
    o.x = sm[(q*4+0)*33 + cr];
    o.y = sm[(q*4+1)*33 + cr];
    o.z = sm[(q*4+2)*33 + cr];
    o.w = sm[(q*4+3)*33 + cr];
    *(float4*)(g_xt + ((size_t)b*TP + SOFF + hw0 + cr)*CC + c0 + q*4) = o;
}

// ---------------- 3x3 conv via mma.sync tf32 implicit GEMM -------------------
__global__ __launch_bounds__(256) void k_convmma(const float* __restrict__ bom) {
    __shared__ float As[128*36];
    __shared__ float Bs[32*120];

    int tid = threadIdx.x, wid = tid >> 5, lane = tid & 31;
    int x = blockIdx.x;
    int s = (x >= 70) + (x >= 90);
    int r = x - SEL3(s, 0, 70, 90);
    int TILES = SEL3(s, 35, 10, 3);
    int b = r / TILES, tile = r % TILES;
    int H = 64 >> s, W = H, HW = H*W, W2 = W + 2, PPn = (H+2)*(W+2);
    int SOFF = SEL3(s, 0, 4096, 5120);
    int p0 = tile*128;
    const float* xb = g_xt + ((size_t)b*TP + SOFF)*CC;

    int q = tid & 7;
    int pyb[4], pxb[4], rowk[4];
    bool ppok[4];
    int bkk[4], bnq[4];
    bool bok[4];
#pragma unroll
    for (int k = 0; k < 4; k++) {
        rowk[k] = (tid >> 3) + 32*k;
        int pp = p0 + rowk[k];
        ppok[k] = pp < PPn;
        pyb[k] = pp / W2 - 1;
        pxb[k] = pp % W2 - 1;
        int u = tid + 256*k;
        bok[k] = u < 896;
        bkk[k] = u / 28;
        bnq[k] = u % 28;
    }

    float4 rA[4], rB[4];
#define LOADI(i) do {                                                            \
    int _t = (i) >> 3, _ck = (i) & 7;                                            \
    int _dy = _t/3 - 1, _dx = _t%3 - 1;                                          \
    _Pragma("unroll")                                                            \
    for (int k = 0; k < 4; k++) {                                                \
        int _py = pyb[k] + _dy, _px = pxb[k] + _dx;                              \
        bool _v = ppok[k] && (unsigned)_py < (unsigned)H && (unsigned)_px < (unsigned)W; \
        float4 _val = make_float4(0.f, 0.f, 0.f, 0.f);                           \
        if (_v) _val = *(const float4*)(xb + (size_t)(_py*W + _px)*CC + _ck*32 + q*4); \
        rA[k] = _val;                                                            \
        float4 _bv = make_float4(0.f, 0.f, 0.f, 0.f);                            \
        if (bok[k]) _bv = *(const float4*)(g_wt + (size_t)(i)*3584 + bkk[k]*112 + bnq[k]*4); \
        rB[k] = _bv;                                                             \
    }                                                                            \
} while (0)

    float d[2][7][4];
#pragma unroll
    for (int mi = 0; mi < 2; mi++)
#pragma unroll
        for (int ni = 0; ni < 7; ni++)
#pragma unroll
            for (int e = 0; e < 4; e++) d[mi][ni][e] = 0.f;

    int wm = wid & 3, wn = wid >> 2;
    int lr = lane >> 2, kc = lane & 3;
    const uint32_t* A32 = (const uint32_t*)As;
    const uint32_t* B32 = (const uint32_t*)Bs;

    LOADI(0);
    for (int i = 0; i < 72; i++) {
        if (i > 0) __syncthreads();
#pragma unroll
        for (int k = 0; k < 4; k++) {
            float4 v = rA[k];
            v.x = tf32r(v.x); v.y = tf32r(v.y); v.z = tf32r(v.z); v.w = tf32r(v.w);
            *(float4*)(As + rowk[k]*36 + q*4) = v;
            if (bok[k]) *(float4*)(Bs + bkk[k]*120 + bnq[k]*4) = rB[k];
        }
        if (i + 1 < 72) LOADI(i + 1);
        __syncthreads();

#pragma unroll
        for (int kq = 0; kq < 32; kq += 8) {
            uint32_t a[2][4];
#pragma unroll
            for (int mi = 0; mi < 2; mi++) {
                int rr = wm*32 + mi*16 + lr;
                a[mi][0] = A32[rr*36 + kq + kc];
                a[mi][1] = A32[(rr+8)*36 + kq + kc];
                a[mi][2] = A32[rr*36 + kq + kc + 4];
                a[mi][3] = A32[(rr+8)*36 + kq + kc + 4];
            }
#pragma unroll
            for (int ni = 0; ni < 7; ni++) {
                int nn = wn*56 + ni*8 + lr;
                uint32_t b0 = B32[(kq+kc)*120 + nn];
                uint32_t b1 = B32[(kq+kc+4)*120 + nn];
                MMA8(d[0][ni], a[0], b0, b1);
                MMA8(d[1][ni], a[1], b0, b1);
            }
        }
    }

    float* obase = g_om + OMOFF(s) + (size_t)b*OMC*HW;
#pragma unroll
    for (int mi = 0; mi < 2; mi++) {
#pragma unroll
        for (int h = 0; h < 2; h++) {
            int pp = p0 + wm*32 + mi*16 + lr + h*8;
            int py = pp / W2 - 1, px = pp % W2 - 1;
            bool ok = (pp < PPn) && (unsigned)py < (unsigned)H && (unsigned)px < (unsigned)W;
            if (!ok) continue;
            float* ob = obase + py*W + px;
#pragma unroll
            for (int ni = 0; ni < 7; ni++) {
                int n = wn*56 + ni*8 + 2*kc;
                if (n < OMC)   ob[(size_t)n*HW]     = d[mi][ni][h*2+0] + bom[n];
                if (n+1 < OMC) ob[(size_t)(n+1)*HW] = d[mi][ni][h*2+1] + bom[n+1];
            }
        }
    }
}

// ---------------- DCN index/weight precompute --------------------------------
// thread per (b*4+g, k, pixel-slot); writes packed {idx, weff} x 4 corners
__global__ __launch_bounds__(256) void k_dcnidx() {
    int p = blockIdx.x*256 + threadIdx.x;      // 0..5375
    int k = blockIdx.y, bg = blockIdx.z;
    int b = bg >> 2, g = bg & 3;
    int s = (p >= 4096) + (p >= 5120);
    int H = 64 >> s, W = H, HW = H*W;
    int SOFF = SEL3(s, 0, 4096, 5120);
    int hw = p - SOFF;
    int h = hw / W, w = hw % W;
    const float* omb = g_om + OMOFF(s) + (size_t)b*OMC*HW;
    int ch = (g*9 + k)*3;
    float offy = omb[(size_t)(ch+0)*HW + hw];
    float offx = omb[(size_t)(ch+1)*HW + hw];
    float msk  = omb[(size_t)(ch+2)*HW + hw];
    int ky = k/3 - 1, kx = k%3 - 1;
    float py = (float)(h + ky) + offy;
    float px = (float)(w + kx) + offx;
    float y0f = floorf(py), x0f = floorf(px);
    float fy = py - y0f, fx = px - x0f;
    int y0 = (int)y0f, x0 = (int)x0f;
    size_t ob = ((size_t)(bg*9 + k)*4)*TP + p;
#pragma unroll
    for (int cr = 0; cr < 4; cr++) {
        int dy = cr >> 1, dx = cr & 1;
        int yy = y0 + dy, xx = x0 + dx;
        float wgt = (dy ? fy : 1.f - fy) * (dx ? fx : 1.f - fx);
        bool valid = (yy >= 0) && (yy < H) && (xx >= 0) && (xx < W);
        float weff = valid ? wgt * msk : 0.f;
        int yc = min(max(yy, 0), H-1);
        int xc = min(max(xx, 0), W-1);
        unsigned idxc = (unsigned)(yc*W + xc);
        g_gpk[ob + (size_t)cr*TP] = (ull)idxc | ((ull)__float_as_uint(weff) << 32);
    }
}

// ---------------- DCNv4 pure gather ------------------------------------------
__global__ __launch_bounds__(256) void k_dcn() {
    int bx = blockIdx.x;
    int warp = threadIdx.x >> 5, lane = threadIdx.x & 31;
    int p = bx*8 + warp;                        // global pixel slot
    int s = (p >= 4096) + (p >= 5120);
    int SOFF = SEL3(s, 0, 4096, 5120);
    int g = blockIdx.y, b = blockIdx.z;
    const float* xb = g_xt + ((size_t)b*TP + SOFF)*CC + g*64;
    const ull* pkb = g_gpk + ((size_t)((b*4 + g)*9)*4)*TP + p;
    ull acc = 0ull;
#pragma unroll
    for (int j = 0; j < 36; j++) {
        ull pk = pkb[(size_t)j*TP];
        float wf = __uint_as_float((unsigned)(pk >> 32));
        unsigned idxc = (unsigned)pk;
        const ull* q = (const ull*)(xb + (size_t)idxc*CC);
        f2fma(acc, f2pk(wf, wf), q[lane]);
    }
    ((ull*)(g_dcn + ((size_t)b*TP + p)*CC + g*64))[lane] = acc;
}

// ---------------- 1x1 projection via mma.sync tf32 ---------------------------
__global__ __launch_bounds__(256) void k_projmma(const float* __restrict__ bp) {
    __shared__ float As[128*36];
    __shared__ float Bs[32*152];

    int tid = threadIdx.x, wid = tid >> 5, lane = tid & 31;
    int m0 = blockIdx.x*128, n0 = blockIdx.y*128;

    int q = tid & 7;
    int rowk[4], bkk[4], bnq[4];
#pragma unroll
    for (int k = 0; k < 4; k++) {
        rowk[k] = (tid >> 3) + 32*k;
        int u = tid + 256*k;
        bkk[k] = u >> 5;
        bnq[k] = u & 31;
    }

    float4 rA[4], rB[4];
#define PLOADI(i) do {                                                           \
    int _k0 = (i)*32;                                                            \
    _Pragma("unroll")                                                            \
    for (int k = 0; k < 4; k++) {                                                \
        rA[k] = *(const float4*)(g_dcn + (size_t)(m0 + rowk[k])*CC + _k0 + q*4); \
        rB[k] = *(const float4*)(g_wpj + (size_t)(_k0 + bkk[k])*CC + n0 + bnq[k]*4); \
    }                                                                            \
} while (0)

    float d[2][8][4];
#pragma unroll
    for (int mi = 0; mi < 2; mi++)
#pragma unroll
        for (int ni = 0; ni < 8; ni++)
#pragma unroll
            for (int e = 0; e < 4; e++) d[mi][ni][e] = 0.f;

    int wm = wid & 3, wn = wid >> 2;
    int lr = lane >> 2, kc = lane & 3;
    const uint32_t* A32 = (const uint32_t*)As;
    const uint32_t* B32 = (const uint32_t*)Bs;

    PLOADI(0);
    for (int i = 0; i < 8; i++) {
        if (i > 0) __syncthreads();
#pragma unroll
        for (int k = 0; k < 4; k++) {
            float4 v = rA[k];
            v.x = tf32r(v.x); v.y = tf32r(v.y); v.z = tf32r(v.z); v.w = tf32r(v.w);
            *(float4*)(As + rowk[k]*36 + q*4) = v;
            *(float4*)(Bs + bkk[k]*152 + bnq[k]*4) = rB[k];
        }
        if (i + 1 < 8) PLOADI(i + 1);
        __syncthreads();

#pragma unroll
        for (int kq = 0; kq < 32; kq += 8) {
            uint32_t a[2][4];
#pragma unroll
            for (int mi = 0; mi < 2; mi++) {
                int rr = wm*32 + mi*16 + lr;
                a[mi][0] = A32[rr*36 + kq + kc];
                a[mi][1] = A32[(rr+8)*36 + kq + kc];
                a[mi][2] = A32[rr*36 + kq + kc + 4];
                a[mi][3] = A32[(rr+8)*36 + kq + kc + 4];
            }
#pragma unroll
            for (int ni = 0; ni < 8; ni++) {
                int nn = wn*64 + ni*8 + lr;
                uint32_t b0 = B32[(kq+kc)*152 + nn];
                uint32_t b1 = B32[(kq+kc+4)*152 + nn];
                MMA8(d[0][ni], a[0], b0, b1);
                MMA8(d[1][ni], a[1], b0, b1);
            }
        }
    }

#pragma unroll
    for (int mi = 0; mi < 2; mi++) {
#pragma unroll
        for (int h = 0; h < 2; h++) {
            int m = m0 + wm*32 + mi*16 + lr + h*8;
            float* orow = g_d + (size_t)m*CC;
#pragma unroll
            for (int ni = 0; ni < 8; ni++) {
                int n = n0 + wn*64 + ni*8 + 2*kc;
                float2 v = make_float2(d[mi][ni][h*2+0] + bp[n],
                                       d[mi][ni][h*2+1] + bp[n+1]);
                *(float2*)(orow + n) = v;
            }
        }
    }
}

// ---------------- channel LayerNorm + sigmoid gate (warp per row) ------------
__global__ __launch_bounds__(256) void k_lngate(const float* __restrict__ lng,
                                                const float* __restrict__ lnb) {
    int warp = threadIdx.x >> 5, lane = threadIdx.x & 31;
    int r = blockIdx.x*8 + warp;
    size_t base = (size_t)r*CC;
    float4 v0 = *(const float4*)(g_d + base + lane*8);
    float4 v1 = *(const float4*)(g_d + base + lane*8 + 4);
    float s = v0.x+v0.y+v0.z+v0.w + v1.x+v1.y+v1.z+v1.w;
    float q = v0.x*v0.x+v0.y*v0.y+v0.z*v0.z+v0.w*v0.w
            + v1.x*v1.x+v1.y*v1.y+v1.z*v1.z+v1.w*v1.w;
#pragma unroll
    for (int o = 16; o; o >>= 1) {
        s += __shfl_xor_sync(0xffffffffu, s, o);
        q += __shfl_xor_sync(0xffffffffu, q, o);
    }
    float mu = s * (1.f/CC);
    float rs = rsqrtf(q * (1.f/CC) - mu*mu + 1e-5f);
    float4 g0 = *(const float4*)(lng + lane*8);
    float4 g1 = *(const float4*)(lng + lane*8 + 4);
    float4 b0 = *(const float4*)(lnb + lane*8);
    float4 b1 = *(const float4*)(lnb + lane*8 + 4);
    float4 x0 = *(const float4*)(g_xt + base + lane*8);
    float4 x1 = *(const float4*)(g_xt + base + lane*8 + 4);
    float4 o0, o1;
    o0.x = x0.x / (1.f + expf(-((v0.x-mu)*rs*g0.x + b0.x)));
    o0.y = x0.y / (1.f + expf(-((v0.y-mu)*rs*g0.y + b0.y)));
    o0.z = x0.z / (1.f + expf(-((v0.z-mu)*rs*g0.z + b0.z)));
    o0.w = x0.w / (1.f + expf(-((v0.w-mu)*rs*g0.w + b0.w)));
    o1.x = x1.x / (1.f + expf(-((v1.x-mu)*rs*g1.x + b1.x)));
    o1.y = x1.y / (1.f + expf(-((v1.y-mu)*rs*g1.y + b1.y)));
    o1.z = x1.z / (1.f + expf(-((v1.z-mu)*rs*g1.z + b1.z)));
    o1.w = x1.w / (1.f + expf(-((v1.w-mu)*rs*g1.w + b1.w)));
    *(float4*)(g_x2t + base + lane*8)     = o0;
    *(float4*)(g_x2t + base + lane*8 + 4) = o1;
}

// ---------------- task attention ---------------------------------------------
__global__ __launch_bounds__(256) void k_pool2a() {
    int slab = blockIdx.x, b = blockIdx.y;
    int s = (slab >= 64) + (slab >= 80);
    int sbase = SEL3(s, 0, 64, 80);
    int SOFF = SEL3(s, 0, 4096, 5120);
    int c = threadIdx.x;
    int r0 = SOFF + (slab - sbase)*64;
    float v = 0.f;
    for (int r = r0; r < r0 + 64; r++)
        v += g_x2t[((size_t)b*TP + r)*CC + c];
    g_part[(b*84 + slab)*CC + c] = v;
}

// merged pool2b + task gemv: 6 blocks (sb = s*NB + b)
__global__ __launch_bounds__(256) void k_task(
        const float* __restrict__ wa1, const float* __restrict__ ba1,
        const float* __restrict__ wb1, const float* __restrict__ bb1,
        const float* __restrict__ wa2, const float* __restrict__ ba2,
        const float* __restrict__ wb2, const float* __restrict__ bb2) {
    __shared__ float sp[256];
    int sb = blockIdx.x;
    int s = sb >> 1, b = sb & 1;
    int slabs = SEL3(s, 64, 16, 4);
    int sbase = SEL3(s, 0, 64, 80);
    int HW = 4096 >> (2*s);
    int tid = threadIdx.x;
    float v = 0.f;
    for (int i = 0; i < slabs; i++) v += g_part[(b*84 + sbase + i)*CC + tid];
    sp[tid] = v / (float)HW;
    __syncthreads();
    int wid = tid >> 5, lane = tid & 31;
    for (int u = wid; u < 1024; u += 8) {
        int which = u >> 8, o = u & 255;
        const float* wr = ((which == 0) ? wa1 : (which == 1) ? wb1 :
                           (which == 2) ? wa2 : wb2) + (size_t)o*CC;
        const float* bs = (which == 0) ? ba1 : (which == 1) ? bb1 :
                          (which == 2) ? ba2 : bb2;
        float vv = 0.f;
#pragma unroll
        for (int i = 0; i < 8; i++) vv = fmaf(wr[lane + i*32], sp[lane + i*32], vv);
#pragma unroll
        for (int o2 = 16; o2; o2 >>= 1) vv += __shfl_down_sync(0xffffffffu, vv, o2);
        if (!lane) g_ab[(which*6 + sb)*CC + o] = fmaxf(vv + bs[o], 0.f);
    }
}

// gated output + transpose (vectorized); x-cum {128,160,168}
__global__ __launch_bounds__(256) void k_taskout(float* __restrict__ out) {
    __shared__ float sm[32*33];
    int bx = blockIdx.x;
    int s = (bx >= 128) + (bx >= 160);
    int base = SEL3(s, 0, 128, 160);
    int HW = 4096 >> (2*s);
    int SOFF = SEL3(s, 0, 4096, 5120);
    size_t OOFF = (size_t)NB*CC*SOFF;
    int b = blockIdx.z;
    int hw0 = (bx - base)*32, c0 = blockIdx.y*32;
    int sb = s*NB + b;
    int t = threadIdx.x;
    int hh = t >> 3, q = t & 7;
    float4 v = *(const float4*)(g_x2t + ((size_t)b*TP + SOFF + hw0 + hh)*CC + c0 + q*4);
    float4 A1 = *(const float4*)(g_ab + (size_t)(0*6 + sb)*CC + c0 + q*4);
    float4 B1 = *(const float4*)(g_ab + (size_t)(1*6 + sb)*CC + c0 + q*4);
    float4 A2 = *(const float4*)(g_ab + (size_t)(2*6 + sb)*CC + c0 + q*4);
    float4 B2 = *(const float4*)(g_ab + (size_t)(3*6 + sb)*CC + c0 + q*4);
    sm[(q*4+0)*33 + hh] = fmaxf(fmaf(A1.x, v.x, B1.x), fmaf(A2.x, v.x, B2.x));
    sm[(q*4+1)*33 + hh] = fmaxf(fmaf(A1.y, v.y, B1.y), fmaf(A2.y, v.y, B2.y));
    sm[(q*4+2)*33 + hh] = fmaxf(fmaf(A1.z, v.z, B1.z), fmaf(A2.z, v.z, B2.z));
    sm[(q*4+3)*33 + hh] = fmaxf(fmaf(A1.w, v.w, B1.w), fmaf(A2.w, v.w, B2.w));
    __syncthreads();
    int cr = t >> 3, q2 = t & 7;
    float4 w;
    w.x = sm[cr*33 + q2*4+0];
    w.y = sm[cr*33 + q2*4+1];
    w.z = sm[cr*33 + q2*4+2];
    w.w = sm[cr*33 + q2*4+3];
    *(float4*)(out + OOFF + ((size_t)b*CC + c0 + cr)*HW + hw0 + q2*4) = w;
}

// ---------------- launch ------------------------------------------------------
extern "C" void kernel_launch(void* const* d_in, const int* in_sizes, int n_in,
                              void* d_out, int out_size) {
    const float* f1 = (const float*)d_in[0];
    const float* f2 = (const float*)d_in[1];
    const float* f3 = (const float*)d_in[2];
    const float* w_scale = (const float*)d_in[3];
    const float* b_scale = (const float*)d_in[4];
    const float* w_om    = (const float*)d_in[5];
    const float* b_om    = (const float*)d_in[6];
    const float* w_proj  = (const float*)d_in[7];
    const float* b_proj  = (const float*)d_in[8];
    const float* ln_g    = (const float*)d_in[9];
    const float* ln_b    = (const float*)d_in[10];
    const float* wa1 = (const float*)d_in[11];
    const float* ba1 = (const float*)d_in[12];
    const float* wb1 = (const float*)d_in[13];
    const float* bb1 = (const float*)d_in[14];
    const float* wa2 = (const float*)d_in[15];
    const float* ba2 = (const float*)d_in[16];
    const float* wb2 = (const float*)d_in[17];
    const float* bb2 = (const float*)d_in[18];
    float* out = (float*)d_out;

    k_prep<<<2800, 256>>>(w_om, w_proj, f1, f2, f3);
    k_scale_gemv<<<(3*NB*CC*32 + 255)/256, 256>>>(w_scale, b_scale);
    k_apply<<<dim3(168, CC/32, NB), 256>>>(f1, f2, f3);
    k_convmma<<<96, 256>>>(b_om);
    k_dcnidx<<<dim3(21, 9, NB*GG), 256>>>();
    k_dcn<<<dim3(672, GG, NB), 256>>>();
    k_projmma<<<dim3(84, 2), 256>>>(b_proj);
    k_lngate<<<NB*TP/8, 256>>>(ln_g, ln_b);
    k_pool2a<<<dim3(84, NB), 256>>>();
    k_task<<<6, 256>>>(wa1, ba1, wb1, bb1, wa2, ba2, wb2, bb2);
    k_taskout<<<dim3(168, CC/32, NB), 256>>>(out);
}

// round 16
// speedup vs baseline: 1.1132x; 1.1132x over previous
#include <cuda_runtime.h>
#include <math.h>
#include <stdint.h>

#define CC    256
#define GG    4
#define NB    2
#define OMC   108          // G*K*3
#define TP    5376         // total pixels per batch across scales (4096+1024+256)
#define POF   (NB*OMC*TP)  // one conv-partial buffer
#define SEL3(s,a,b,c) ((s)==0 ? (a) : ((s)==1 ? (b) : (c)))

typedef unsigned long long ull;

__device__ __forceinline__ ull f2pk(float lo, float hi) {
    ull r; asm("mov.b64 %0, {%1, %2};" : "=l"(r) : "f"(lo), "f"(hi)); return r;
}
__device__ __forceinline__ void f2fma(ull &d, ull a, ull b) {
    asm("fma.rn.f32x2 %0, %1, %2, %0;" : "+l"(d) : "l"(a), "l"(b));
}
__device__ __forceinline__ float2 f2up(ull v) {
    float2 o; asm("mov.b64 {%0, %1}, %2;" : "=f"(o.x), "=f"(o.y) : "l"(v)); return o;
}
__device__ __forceinline__ float tf32r(float x) {
    float r; asm("cvt.rna.tf32.f32 %0, %1;" : "=f"(r) : "f"(x)); return r;
}

// warp-level tf32 MMA (sm_80+ path; compiles on plain sm_103)
#define MMA8(d, a, b0, b1) \
    asm volatile("mma.sync.aligned.m16n8k8.row.col.f32.tf32.tf32.f32 " \
        "{%0,%1,%2,%3}, {%4,%5,%6,%7}, {%8,%9}, {%0,%1,%2,%3};" \
        : "+f"((d)[0]), "+f"((d)[1]), "+f"((d)[2]), "+f"((d)[3]) \
        : "r"((a)[0]), "r"((a)[1]), "r"((a)[2]), "r"((a)[3]), "r"(b0), "r"(b1))

// ---------------- scratch (static device globals) ---------------------------
__device__ float g_xt [NB*TP*CC];        // scaled input, pixel-major [b][p][c]
__device__ float g_omp[2*POF];           // conv output partials (K-split halves)
__device__ float g_dcn[NB*TP*CC];
__device__ float g_d  [NB*TP*CC];
__device__ float g_x2t[NB*TP*CC];
__device__ float g_wt [72*32*112];       // conv weights tf32: [tap*8+ck][kk(32)][n(112)]
__device__ float g_wpj[CC*CC];           // proj weights tf32, transposed: [k][n]
__device__ ull   g_gpk[NB*GG*9*4*TP];    // packed {idx, weff} per (b,g,k,corner,pixel)
__device__ float g_pool [3*NB*CC];
__device__ float g_sfac [3*NB*CC];
__device__ float g_part [NB*84*CC];
__device__ float g_ab  [4*3*NB*CC];

#define OMOFF(s) SEL3(s, 0, 884736, 1105920)

// ---------------- merged prep: conv weights + proj transpose + pool ----------
__global__ __launch_bounds__(256) void k_prep(const float* __restrict__ wom,
                                              const float* __restrict__ wp,
                                              const float* __restrict__ f1,
                                              const float* __restrict__ f2,
                                              const float* __restrict__ f3) {
    int bx = blockIdx.x;
    if (bx < 1008) {
        int idx = bx*256 + threadIdx.x;
        int i = idx / 3584, r = idx % 3584, kk = r / 112, n = r % 112;
        int t = i >> 3, ck = i & 7, c = ck*32 + kk;
        float v = (n < OMC) ? wom[n*2304 + c*9 + t] : 0.f;
        g_wt[idx] = tf32r(v);
    } else if (bx < 1264) {
        int idx = (bx - 1008)*256 + threadIdx.x;   // < 65536
        int k = idx >> 8, n = idx & 255;
        g_wpj[idx] = tf32r(wp[n*CC + k]);
    } else {
        int pb = bx - 1264;                        // < 1536
        int c = pb & 255, b = (pb >> 8) & 1, s = pb >> 9;
        int HW = 4096 >> (2*s);
        const float* x = SEL3(s, f1, f2, f3);
        const float* p = x + ((size_t)b*CC + c)*HW;
        float v = 0.f;
        for (int i = threadIdx.x; i < HW; i += 256) v += p[i];
        __shared__ float sm[8];
        int lane = threadIdx.x & 31, wid = threadIdx.x >> 5;
#pragma unroll
        for (int o = 16; o; o >>= 1) v += __shfl_down_sync(0xffffffffu, v, o);
        if (!lane) sm[wid] = v;
        __syncthreads();
        if (threadIdx.x == 0) {
            float t = 0.f;
#pragma unroll
            for (int i = 0; i < 8; i++) t += sm[i];
            g_pool[(s*NB + b)*CC + c] = t / (float)HW;
        }
    }
}

__global__ __launch_bounds__(256) void k_scale_gemv(const float* __restrict__ wsc,
                                                    const float* __restrict__ bsc) {
    int gw = (blockIdx.x*blockDim.x + threadIdx.x) >> 5;
    int lane = threadIdx.x & 31;
    if (gw >= 3*NB*CC) return;
    int sb = gw / CC, o = gw % CC;
    const float* wr = wsc + (size_t)o*CC;
    const float* pr = g_pool + sb*CC;
    float v = 0.f;
#pragma unroll
    for (int i = 0; i < CC/32; i++) v = fmaf(wr[lane + i*32], pr[lane + i*32], v);
#pragma unroll
    for (int o2 = 16; o2; o2 >>= 1) v += __shfl_down_sync(0xffffffffu, v, o2);
    if (!lane) {
        v = (v + bsc[o] + 1.f) * 0.5f;
        g_sfac[sb*CC + o] = fminf(fmaxf(v, 0.f), 1.f);
    }
}

// scale + transpose to pixel-major (vectorized; x-tile cum {128,160,168})
__global__ __launch_bounds__(256) void k_apply(const float* __restrict__ f1,
                                               const float* __restrict__ f2,
                                               const float* __restrict__ f3) {
    __shared__ float sm[32*33];
    int bx = blockIdx.x;
    int s = (bx >= 128) + (bx >= 160);
    int base = SEL3(s, 0, 128, 160);
    int HW = 4096 >> (2*s);
    int SOFF = SEL3(s, 0, 4096, 5120);
    const float* x = SEL3(s, f1, f2, f3);
    int b = blockIdx.z;
    int hw0 = (bx - base)*32, c0 = blockIdx.y*32;
    int t = threadIdx.x;
    int cr = t >> 3, q = t & 7;
    float4 v = *(const float4*)(x + ((size_t)b*CC + c0 + cr)*HW + hw0 + q*4);
    float sf = g_sfac[(s*NB + b)*CC + c0 + cr];
    sm[cr*33 + q*4+0] = v.x*sf;
    sm[cr*33 + q*4+1] = v.y*sf;
    sm[cr*33 + q*4+2] = v.z*sf;
    sm[cr*33 + q*4+3] = v.w*sf;
    __syncthreads();
    float4 o;
    o.x = sm[(q*4+0)*33 + cr];
    o.y = sm[(q*4+1)*33 + cr];
    o.z = sm[(q*4+2)*33 + cr];
    o.w = sm[(q*4+3)*33 + cr];
    *(float4*)(g_xt + ((size_t)b*TP + SOFF + hw0 + cr)*CC + c0 + q*4) = o;
}

// ---------------- 3x3 conv via mma.sync tf32 implicit GEMM -------------------
// 2-way K-split: grid 192; CTA handles 36 of 72 K-iterations, writes partial.
__global__ __launch_bounds__(256,2) void k_convmma() {
    __shared__ float As[128*36];
    __shared__ float Bs[32*120];

    int tid = threadIdx.x, wid = tid >> 5, lane = tid & 31;
    int x2 = blockIdx.x;
    int half = x2 >= 96;
    int x = x2 - 96*half;
    int s = (x >= 70) + (x >= 90);
    int r = x - SEL3(s, 0, 70, 90);
    int TILES = SEL3(s, 35, 10, 3);
    int b = r / TILES, tile = r % TILES;
    int H = 64 >> s, W = H, HW = H*W, W2 = W + 2, PPn = (H+2)*(W+2);
    int SOFF = SEL3(s, 0, 4096, 5120);
    int p0 = tile*128;
    const float* xb = g_xt + ((size_t)b*TP + SOFF)*CC;

    int q = tid & 7;
    int pyb[4], pxb[4], rowk[4];
    bool ppok[4];
    int bkk[4], bnq[4];
    bool bok[4];
#pragma unroll
    for (int k = 0; k < 4; k++) {
        rowk[k] = (tid >> 3) + 32*k;
        int pp = p0 + rowk[k];
        ppok[k] = pp < PPn;
        pyb[k] = pp / W2 - 1;
        pxb[k] = pp % W2 - 1;
        int u = tid + 256*k;
        bok[k] = u < 896;
        bkk[k] = u / 28;
        bnq[k] = u % 28;
    }

    float4 rA[4], rB[4];
#define LOADI(i) do {                                                            \
    int _t = (i) >> 3, _ck = (i) & 7;                                            \
    int _dy = _t/3 - 1, _dx = _t%3 - 1;                                          \
    _Pragma("unroll")                                                            \
    for (int k = 0; k < 4; k++) {                                                \
        int _py = pyb[k] + _dy, _px = pxb[k] + _dx;                              \
        bool _v = ppok[k] && (unsigned)_py < (unsigned)H && (unsigned)_px < (unsigned)W; \
        float4 _val = make_float4(0.f, 0.f, 0.f, 0.f);                           \
        if (_v) _val = *(const float4*)(xb + (size_t)(_py*W + _px)*CC + _ck*32 + q*4); \
        rA[k] = _val;                                                            \
        float4 _bv = make_float4(0.f, 0.f, 0.f, 0.f);                            \
        if (bok[k]) _bv = *(const float4*)(g_wt + (size_t)(i)*3584 + bkk[k]*112 + bnq[k]*4); \
        rB[k] = _bv;                                                             \
    }                                                                            \
} while (0)

    float d[2][7][4];
#pragma unroll
    for (int mi = 0; mi < 2; mi++)
#pragma unroll
        for (int ni = 0; ni < 7; ni++)
#pragma unroll
            for (int e = 0; e < 4; e++) d[mi][ni][e] = 0.f;

    int wm = wid & 3, wn = wid >> 2;
    int lr = lane >> 2, kc = lane & 3;
    const uint32_t* A32 = (const uint32_t*)As;
    const uint32_t* B32 = (const uint32_t*)Bs;

    int i0 = half*36, i1 = i0 + 36;
    LOADI(i0);
    for (int i = i0; i < i1; i++) {
        if (i > i0) __syncthreads();
#pragma unroll
        for (int k = 0; k < 4; k++) {
            float4 v = rA[k];
            v.x = tf32r(v.x); v.y = tf32r(v.y); v.z = tf32r(v.z); v.w = tf32r(v.w);
            *(float4*)(As + rowk[k]*36 + q*4) = v;
            if (bok[k]) *(float4*)(Bs + bkk[k]*120 + bnq[k]*4) = rB[k];
        }
        if (i + 1 < i1) LOADI(i + 1);
        __syncthreads();

#pragma unroll
        for (int kq = 0; kq < 32; kq += 8) {
            uint32_t a[2][4];
#pragma unroll
            for (int mi = 0; mi < 2; mi++) {
                int rr = wm*32 + mi*16 + lr;
                a[mi][0] = A32[rr*36 + kq + kc];
                a[mi][1] = A32[(rr+8)*36 + kq + kc];
                a[mi][2] = A32[rr*36 + kq + kc + 4];
                a[mi][3] = A32[(rr+8)*36 + kq + kc + 4];
            }
#pragma unroll
            for (int ni = 0; ni < 7; ni++) {
                int nn = wn*56 + ni*8 + lr;
                uint32_t b0 = B32[(kq+kc)*120 + nn];
                uint32_t b1 = B32[(kq+kc+4)*120 + nn];
                MMA8(d[0][ni], a[0], b0, b1);
                MMA8(d[1][ni], a[1], b0, b1);
            }
        }
    }

    float* obase = g_omp + (size_t)half*POF + OMOFF(s) + (size_t)b*OMC*HW;
#pragma unroll
    for (int mi = 0; mi < 2; mi++) {
#pragma unroll
        for (int h = 0; h < 2; h++) {
            int pp = p0 + wm*32 + mi*16 + lr + h*8;
            int py = pp / W2 - 1, px = pp % W2 - 1;
            bool ok = (pp < PPn) && (unsigned)py < (unsigned)H && (unsigned)px < (unsigned)W;
            if (!ok) continue;
            float* ob = obase + py*W + px;
#pragma unroll
            for (int ni = 0; ni < 7; ni++) {
                int n = wn*56 + ni*8 + 2*kc;
                if (n < OMC)   ob[(size_t)n*HW]     = d[mi][ni][h*2+0];
                if (n+1 < OMC) ob[(size_t)(n+1)*HW] = d[mi][ni][h*2+1];
            }
        }
    }
}

// ---------------- DCN index/weight precompute (sums conv partials + bias) ----
__global__ __launch_bounds__(256) void k_dcnidx(const float* __restrict__ bom) {
    int p = blockIdx.x*256 + threadIdx.x;      // 0..5375
    int k = blockIdx.y, bg = blockIdx.z;
    int b = bg >> 2, g = bg & 3;
    int s = (p >= 4096) + (p >= 5120);
    int H = 64 >> s, W = H, HW = H*W;
    int SOFF = SEL3(s, 0, 4096, 5120);
    int hw = p - SOFF;
    int h = hw / W, w = hw % W;
    const float* om0 = g_omp + OMOFF(s) + (size_t)b*OMC*HW;
    const float* om1 = om0 + POF;
    int ch = (g*9 + k)*3;
    float offy = om0[(size_t)(ch+0)*HW + hw] + om1[(size_t)(ch+0)*HW + hw] + bom[ch+0];
    float offx = om0[(size_t)(ch+1)*HW + hw] + om1[(size_t)(ch+1)*HW + hw] + bom[ch+1];
    float msk  = om0[(size_t)(ch+2)*HW + hw] + om1[(size_t)(ch+2)*HW + hw] + bom[ch+2];
    int ky = k/3 - 1, kx = k%3 - 1;
    float py = (float)(h + ky) + offy;
    float px = (float)(w + kx) + offx;
    float y0f = floorf(py), x0f = floorf(px);
    float fy = py - y0f, fx = px - x0f;
    int y0 = (int)y0f, x0 = (int)x0f;
    size_t ob = ((size_t)(bg*9 + k)*4)*TP + p;
#pragma unroll
    for (int cr = 0; cr < 4; cr++) {
        int dy = cr >> 1, dx = cr & 1;
        int yy = y0 + dy, xx = x0 + dx;
        float wgt = (dy ? fy : 1.f - fy) * (dx ? fx : 1.f - fx);
        bool valid = (yy >= 0) && (yy < H) && (xx >= 0) && (xx < W);
        float weff = valid ? wgt * msk : 0.f;
        int yc = min(max(yy, 0), H-1);
        int xc = min(max(xx, 0), W-1);
        unsigned idxc = (unsigned)(yc*W + xc);
        g_gpk[ob + (size_t)cr*TP] = (ull)idxc | ((ull)__float_as_uint(weff) << 32);
    }
}

// ---------------- DCNv4 pure gather ------------------------------------------
__global__ __launch_bounds__(256) void k_dcn() {
    int bx = blockIdx.x;
    int warp = threadIdx.x >> 5, lane = threadIdx.x & 31;
    int p = bx*8 + warp;                        // global pixel slot
    int s = (p >= 4096) + (p >= 5120);
    int SOFF = SEL3(s, 0, 4096, 5120);
    int g = blockIdx.y, b = blockIdx.z;
    const float* xb = g_xt + ((size_t)b*TP + SOFF)*CC + g*64;
    const ull* pkb = g_gpk + ((size_t)((b*4 + g)*9)*4)*TP + p;
    ull acc = 0ull;
#pragma unroll
    for (int j = 0; j < 36; j++) {
        ull pk = pkb[(size_t)j*TP];
        float wf = __uint_as_float((unsigned)(pk >> 32));
        unsigned idxc = (unsigned)pk;
        const ull* q = (const ull*)(xb + (size_t)idxc*CC);
        f2fma(acc, f2pk(wf, wf), q[lane]);
    }
    ((ull*)(g_dcn + ((size_t)b*TP + p)*CC + g*64))[lane] = acc;
}

// ---------------- 1x1 projection via mma.sync tf32 ---------------------------
__global__ __launch_bounds__(256) void k_projmma(const float* __restrict__ bp) {
    __shared__ float As[128*36];
    __shared__ float Bs[32*152];

    int tid = threadIdx.x, wid = tid >> 5, lane = tid & 31;
    int m0 = blockIdx.x*128, n0 = blockIdx.y*128;

    int q = tid & 7;
    int rowk[4], bkk[4], bnq[4];
#pragma unroll
    for (int k = 0; k < 4; k++) {
        rowk[k] = (tid >> 3) + 32*k;
        int u = tid + 256*k;
        bkk[k] = u >> 5;
        bnq[k] = u & 31;
    }

    float4 rA[4], rB[4];
#define PLOADI(i) do {                                                           \
    int _k0 = (i)*32;                                                            \
    _Pragma("unroll")                                                            \
    for (int k = 0; k < 4; k++) {                                                \
        rA[k] = *(const float4*)(g_dcn + (size_t)(m0 + rowk[k])*CC + _k0 + q*4); \
        rB[k] = *(const float4*)(g_wpj + (size_t)(_k0 + bkk[k])*CC + n0 + bnq[k]*4); \
    }                                                                            \
} while (0)

    float d[2][8][4];
#pragma unroll
    for (int mi = 0; mi < 2; mi++)
#pragma unroll
        for (int ni = 0; ni < 8; ni++)
#pragma unroll
            for (int e = 0; e < 4; e++) d[mi][ni][e] = 0.f;

    int wm = wid & 3, wn = wid >> 2;
    int lr = lane >> 2, kc = lane & 3;
    const uint32_t* A32 = (const uint32_t*)As;
    const uint32_t* B32 = (const uint32_t*)Bs;

    PLOADI(0);
    for (int i = 0; i < 8; i++) {
        if (i > 0) __syncthreads();
#pragma unroll
        for (int k = 0; k < 4; k++) {
            float4 v = rA[k];
            v.x = tf32r(v.x); v.y = tf32r(v.y); v.z = tf32r(v.z); v.w = tf32r(v.w);
            *(float4*)(As + rowk[k]*36 + q*4) = v;
            *(float4*)(Bs + bkk[k]*152 + bnq[k]*4) = rB[k];
        }
        if (i + 1 < 8) PLOADI(i + 1);
        __syncthreads();

#pragma unroll
        for (int kq = 0; kq < 32; kq += 8) {
            uint32_t a[2][4];
#pragma unroll
            for (int mi = 0; mi < 2; mi++) {
                int rr = wm*32 + mi*16 + lr;
                a[mi][0] = A32[rr*36 + kq + kc];
                a[mi][1] = A32[(rr+8)*36 + kq + kc];
                a[mi][2] = A32[rr*36 + kq + kc + 4];
                a[mi][3] = A32[(rr+8)*36 + kq + kc + 4];
            }
#pragma unroll
            for (int ni = 0; ni < 8; ni++) {
                int nn = wn*64 + ni*8 + lr;
                uint32_t b0 = B32[(kq+kc)*152 + nn];
                uint32_t b1 = B32[(kq+kc+4)*152 + nn];
                MMA8(d[0][ni], a[0], b0, b1);
                MMA8(d[1][ni], a[1], b0, b1);
            }
        }
    }

#pragma unroll
    for (int mi = 0; mi < 2; mi++) {
#pragma unroll
        for (int h = 0; h < 2; h++) {
            int m = m0 + wm*32 + mi*16 + lr + h*8;
            float* orow = g_d + (size_t)m*CC;
#pragma unroll
            for (int ni = 0; ni < 8; ni++) {
                int n = n0 + wn*64 + ni*8 + 2*kc;
                float2 v = make_float2(d[mi][ni][h*2+0] + bp[n],
                                       d[mi][ni][h*2+1] + bp[n+1]);
                *(float2*)(orow + n) = v;
            }
        }
    }
}

// ---------------- channel LayerNorm + sigmoid gate (warp per row) ------------
__global__ __launch_bounds__(256) void k_lngate(const float* __restrict__ lng,
                                                const float* __restrict__ lnb) {
    int warp = threadIdx.x >> 5, lane = threadIdx.x & 31;
    int r = blockIdx.x*8 + warp;
    size_t base = (size_t)r*CC;
    float4 v0 = *(const float4*)(g_d + base + lane*8);
    float4 v1 = *(const float4*)(g_d + base + lane*8 + 4);
    float s = v0.x+v0.y+v0.z+v0.w + v1.x+v1.y+v1.z+v1.w;
    float q = v0.x*v0.x+v0.y*v0.y+v0.z*v0.z+v0.w*v0.w
            + v1.x*v1.x+v1.y*v1.y+v1.z*v1.z+v1.w*v1.w;
#pragma unroll
    for (int o = 16; o; o >>= 1) {
        s += __shfl_xor_sync(0xffffffffu, s, o);
        q += __shfl_xor_sync(0xffffffffu, q, o);
    }
    float mu = s * (1.f/CC);
    float rs = rsqrtf(q * (1.f/CC) - mu*mu + 1e-5f);
    float4 g0 = *(const float4*)(lng + lane*8);
    float4 g1 = *(const float4*)(lng + lane*8 + 4);
    float4 b0 = *(const float4*)(lnb + lane*8);
    float4 b1 = *(const float4*)(lnb + lane*8 + 4);
    float4 x0 = *(const float4*)(g_xt + base + lane*8);
    float4 x1 = *(const float4*)(g_xt + base + lane*8 + 4);
    float4 o0, o1;
    o0.x = x0.x / (1.f + expf(-((v0.x-mu)*rs*g0.x + b0.x)));
    o0.y = x0.y / (1.f + expf(-((v0.y-mu)*rs*g0.y + b0.y)));
    o0.z = x0.z / (1.f + expf(-((v0.z-mu)*rs*g0.z + b0.z)));
    o0.w = x0.w / (1.f + expf(-((v0.w-mu)*rs*g0.w + b0.w)));
    o1.x = x1.x / (1.f + expf(-((v1.x-mu)*rs*g1.x + b1.x)));
    o1.y = x1.y / (1.f + expf(-((v1.y-mu)*rs*g1.y + b1.y)));
    o1.z = x1.z / (1.f + expf(-((v1.z-mu)*rs*g1.z + b1.z)));
    o1.w = x1.w / (1.f + expf(-((v1.w-mu)*rs*g1.w + b1.w)));
    *(float4*)(g_x2t + base + lane*8)     = o0;
    *(float4*)(g_x2t + base + lane*8 + 4) = o1;
}

// ---------------- task attention ---------------------------------------------
__global__ __launch_bounds__(256) void k_pool2a() {
    int slab = blockIdx.x, b = blockIdx.y;
    int s = (slab >= 64) + (slab >= 80);
    int sbase = SEL3(s, 0, 64, 80);
    int SOFF = SEL3(s, 0, 4096, 5120);
    int c = threadIdx.x;
    int r0 = SOFF + (slab - sbase)*64;
    float v = 0.f;
    for (int r = r0; r < r0 + 64; r++)
        v += g_x2t[((size_t)b*TP + r)*CC + c];
    g_part[(b*84 + slab)*CC + c] = v;
}

// merged pool2b + task gemv: 6 blocks (sb = s*NB + b)
__global__ __launch_bounds__(256) void k_task(
        const float* __restrict__ wa1, const float* __restrict__ ba1,
        const float* __restrict__ wb1, const float* __restrict__ bb1,
        const float* __restrict__ wa2, const float* __restrict__ ba2,
        const float* __restrict__ wb2, const float* __restrict__ bb2) {
    __shared__ float sp[256];
    int sb = blockIdx.x;
    int s = sb >> 1, b = sb & 1;
    int slabs = SEL3(s, 64, 16, 4);
    int sbase = SEL3(s, 0, 64, 80);
    int HW = 4096 >> (2*s);
    int tid = threadIdx.x;
    float v = 0.f;
    for (int i = 0; i < slabs; i++) v += g_part[(b*84 + sbase + i)*CC + tid];
    sp[tid] = v / (float)HW;
    __syncthreads();
    int wid = tid >> 5, lane = tid & 31;
    for (int u = wid; u < 1024; u += 8) {
        int which = u >> 8, o = u & 255;
        const float* wr = ((which == 0) ? wa1 : (which == 1) ? wb1 :
                           (which == 2) ? wa2 : wb2) + (size_t)o*CC;
        const float* bs = (which == 0) ? ba1 : (which == 1) ? bb1 :
                          (which == 2) ? ba2 : bb2;
        float vv = 0.f;
#pragma unroll
        for (int i = 0; i < 8; i++) vv = fmaf(wr[lane + i*32], sp[lane + i*32], vv);
#pragma unroll
        for (int o2 = 16; o2; o2 >>= 1) vv += __shfl_down_sync(0xffffffffu, vv, o2);
        if (!lane) g_ab[(which*6 + sb)*CC + o] = fmaxf(vv + bs[o], 0.f);
    }
}

// gated output + transpose (vectorized); x-cum {128,160,168}
__global__ __launch_bounds__(256) void k_taskout(float* __restrict__ out) {
    __shared__ float sm[32*33];
    int bx = blockIdx.x;
    int s = (bx >= 128) + (bx >= 160);
    int base = SEL3(s, 0, 128, 160);
    int HW = 4096 >> (2*s);
    int SOFF = SEL3(s, 0, 4096, 5120);
    size_t OOFF = (size_t)NB*CC*SOFF;
    int b = blockIdx.z;
    int hw0 = (bx - base)*32, c0 = blockIdx.y*32;
    int sb = s*NB + b;
    int t = threadIdx.x;
    int hh = t >> 3, q = t & 7;
    float4 v = *(const float4*)(g_x2t + ((size_t)b*TP + SOFF + hw0 + hh)*CC + c0 + q*4);
    float4 A1 = *(const float4*)(g_ab + (size_t)(0*6 + sb)*CC + c0 + q*4);
    float4 B1 = *(const float4*)(g_ab + (size_t)(1*6 + sb)*CC + c0 + q*4);
    float4 A2 = *(const float4*)(g_ab + (size_t)(2*6 + sb)*CC + c0 + q*4);
    float4 B2 = *(const float4*)(g_ab + (size_t)(3*6 + sb)*CC + c0 + q*4);
    sm[(q*4+0)*33 + hh] = fmaxf(fmaf(A1.x, v.x, B1.x), fmaf(A2.x, v.x, B2.x));
    sm[(q*4+1)*33 + hh] = fmaxf(fmaf(A1.y, v.y, B1.y), fmaf(A2.y, v.y, B2.y));
    sm[(q*4+2)*33 + hh] = fmaxf(fmaf(A1.z, v.z, B1.z), fmaf(A2.z, v.z, B2.z));
    sm[(q*4+3)*33 + hh] = fmaxf(fmaf(A1.w, v.w, B1.w), fmaf(A2.w, v.w, B2.w));
    __syncthreads();
    int cr = t >> 3, q2 = t & 7;
    float4 w;
    w.x = sm[cr*33 + q2*4+0];
    w.y = sm[cr*33 + q2*4+1];
    w.z = sm[cr*33 + q2*4+2];
    w.w = sm[cr*33 + q2*4+3];
    *(float4*)(out + OOFF + ((size_t)b*CC + c0 + cr)*HW + hw0 + q2*4) = w;
}

// ---------------- launch ------------------------------------------------------
extern "C" void kernel_launch(void* const* d_in, const int* in_sizes, int n_in,
                              void* d_out, int out_size) {
    const float* f1 = (const float*)d_in[0];
    const float* f2 = (const float*)d_in[1];
    const float* f3 = (const float*)d_in[2];
    const float* w_scale = (const float*)d_in[3];
    const float* b_scale = (const float*)d_in[4];
    const float* w_om    = (const float*)d_in[5];
    const float* b_om    = (const float*)d_in[6];
    const float* w_proj  = (const float*)d_in[7];
    const float* b_proj  = (const float*)d_in[8];
    const float* ln_g    = (const float*)d_in[9];
    const float* ln_b    = (const float*)d_in[10];
    const float* wa1 = (const float*)d_in[11];
    const float* ba1 = (const float*)d_in[12];
    const float* wb1 = (const float*)d_in[13];
    const float* bb1 = (const float*)d_in[14];
    const float* wa2 = (const float*)d_in[15];
    const float* ba2 = (const float*)d_in[16];
    const float* wb2 = (const float*)d_in[17];
    const float* bb2 = (const float*)d_in[18];
    float* out = (float*)d_out;

    k_prep<<<2800, 256>>>(w_om, w_proj, f1, f2, f3);
    k_scale_gemv<<<(3*NB*CC*32 + 255)/256, 256>>>(w_scale, b_scale);
    k_apply<<<dim3(168, CC/32, NB), 256>>>(f1, f2, f3);
    k_convmma<<<192, 256>>>();
    k_dcnidx<<<dim3(21, 9, NB*GG), 256>>>(b_om);
    k_dcn<<<dim3(672, GG, NB), 256>>>();
    k_projmma<<<dim3(84, 2), 256>>>(b_proj);
    k_lngate<<<NB*TP/8, 256>>>(ln_g, ln_b);
    k_pool2a<<<dim3(84, NB), 256>>>();
    k_task<<<6, 256>>>(wa1, ba1, wb1, bb1, wa2, ba2, wb2, bb2);
    k_taskout<<<dim3(168, CC/32, NB), 256>>>(out);
}

// round 17
// speedup vs baseline: 1.1332x; 1.0179x over previous
#include <cuda_runtime.h>
#include <math.h>
#include <stdint.h>

#define CC    256
#define GG    4
#define NB    2
#define OMC   108          // G*K*3
#define TP    5376         // total pixels per batch across scales (4096+1024+256)
#define POF   (NB*OMC*TP)  // one conv-partial buffer
#define SEL3(s,a,b,c) ((s)==0 ? (a) : ((s)==1 ? (b) : (c)))

typedef unsigned long long ull;

__device__ __forceinline__ ull f2pk(float lo, float hi) {
    ull r; asm("mov.b64 %0, {%1, %2};" : "=l"(r) : "f"(lo), "f"(hi)); return r;
}
__device__ __forceinline__ void f2fma(ull &d, ull a, ull b) {
    asm("fma.rn.f32x2 %0, %1, %2, %0;" : "+l"(d) : "l"(a), "l"(b));
}
__device__ __forceinline__ float2 f2up(ull v) {
    float2 o; asm("mov.b64 {%0, %1}, %2;" : "=f"(o.x), "=f"(o.y) : "l"(v)); return o;
}
__device__ __forceinline__ float tf32r(float x) {
    float r; asm("cvt.rna.tf32.f32 %0, %1;" : "=f"(r) : "f"(x)); return r;
}

// warp-level tf32 MMA (sm_80+ path; compiles on plain sm_103)
#define MMA8(d, a, b0, b1) \
    asm volatile("mma.sync.aligned.m16n8k8.row.col.f32.tf32.tf32.f32 " \
        "{%0,%1,%2,%3}, {%4,%5,%6,%7}, {%8,%9}, {%0,%1,%2,%3};" \
        : "+f"((d)[0]), "+f"((d)[1]), "+f"((d)[2]), "+f"((d)[3]) \
        : "r"((a)[0]), "r"((a)[1]), "r"((a)[2]), "r"((a)[3]), "r"(b0), "r"(b1))

// ---------------- scratch (static device globals) ---------------------------
__device__ float g_xt [NB*TP*CC];        // scaled input, pixel-major [b][p][c]
__device__ float g_omp[3*POF];           // conv output partials (K-split thirds)
__device__ float g_dcn[NB*TP*CC];
__device__ float g_d  [NB*TP*CC];
__device__ float g_x2t[NB*TP*CC];
__device__ float g_wt [72*32*112];       // conv weights tf32: [tap*8+ck][kk(32)][n(112)]
__device__ float g_wpj[CC*CC];           // proj weights tf32, transposed: [k][n]
__device__ ull   g_gpk[NB*GG*9*4*TP];    // packed {idx, weff} per (b,g,k,corner,pixel)
__device__ float g_pool [3*NB*CC];
__device__ float g_sfac [3*NB*CC];
__device__ float g_part [NB*84*CC];
__device__ float g_ab  [4*3*NB*CC];

#define OMOFF(s) SEL3(s, 0, 884736, 1105920)

// conv dynamic smem: 2 x A(128*36) + 2 x B(32*120) floats
#define CVA 4608
#define CVB 3840
#define CSMEM ((2*CVA + 2*CVB)*4)

// ---------------- merged prep: conv weights + proj transpose + pool ----------
__global__ __launch_bounds__(256) void k_prep(const float* __restrict__ wom,
                                              const float* __restrict__ wp,
                                              const float* __restrict__ f1,
                                              const float* __restrict__ f2,
                                              const float* __restrict__ f3) {
    int bx = blockIdx.x;
    if (bx < 1008) {
        int idx = bx*256 + threadIdx.x;
        int i = idx / 3584, r = idx % 3584, kk = r / 112, n = r % 112;
        int t = i >> 3, ck = i & 7, c = ck*32 + kk;
        float v = (n < OMC) ? wom[n*2304 + c*9 + t] : 0.f;
        g_wt[idx] = tf32r(v);
    } else if (bx < 1264) {
        int idx = (bx - 1008)*256 + threadIdx.x;   // < 65536
        int k = idx >> 8, n = idx & 255;
        g_wpj[idx] = tf32r(wp[n*CC + k]);
    } else {
        int pb = bx - 1264;                        // < 1536
        int c = pb & 255, b = (pb >> 8) & 1, s = pb >> 9;
        int HW = 4096 >> (2*s);
        const float* x = SEL3(s, f1, f2, f3);
        const float* p = x + ((size_t)b*CC + c)*HW;
        float v = 0.f;
        for (int i = threadIdx.x; i < HW; i += 256) v += p[i];
        __shared__ float sm[8];
        int lane = threadIdx.x & 31, wid = threadIdx.x >> 5;
#pragma unroll
        for (int o = 16; o; o >>= 1) v += __shfl_down_sync(0xffffffffu, v, o);
        if (!lane) sm[wid] = v;
        __syncthreads();
        if (threadIdx.x == 0) {
            float t = 0.f;
#pragma unroll
            for (int i = 0; i < 8; i++) t += sm[i];
            g_pool[(s*NB + b)*CC + c] = t / (float)HW;
        }
    }
}

__global__ __launch_bounds__(256) void k_scale_gemv(const float* __restrict__ wsc,
                                                    const float* __restrict__ bsc) {
    int gw = (blockIdx.x*blockDim.x + threadIdx.x) >> 5;
    int lane = threadIdx.x & 31;
    if (gw >= 3*NB*CC) return;
    int sb = gw / CC, o = gw % CC;
    const float* wr = wsc + (size_t)o*CC;
    const float* pr = g_pool + sb*CC;
    float v = 0.f;
#pragma unroll
    for (int i = 0; i < CC/32; i++) v = fmaf(wr[lane + i*32], pr[lane + i*32], v);
#pragma unroll
    for (int o2 = 16; o2; o2 >>= 1) v += __shfl_down_sync(0xffffffffu, v, o2);
    if (!lane) {
        v = (v + bsc[o] + 1.f) * 0.5f;
        g_sfac[sb*CC + o] = fminf(fmaxf(v, 0.f), 1.f);
    }
}

// scale + transpose to pixel-major (vectorized; x-tile cum {128,160,168})
__global__ __launch_bounds__(256) void k_apply(const float* __restrict__ f1,
                                               const float* __restrict__ f2,
                                               const float* __restrict__ f3) {
    __shared__ float sm[32*33];
    int bx = blockIdx.x;
    int s = (bx >= 128) + (bx >= 160);
    int base = SEL3(s, 0, 128, 160);
    int HW = 4096 >> (2*s);
    int SOFF = SEL3(s, 0, 4096, 5120);
    const float* x = SEL3(s, f1, f2, f3);
    int b = blockIdx.z;
    int hw0 = (bx - base)*32, c0 = blockIdx.y*32;
    int t = threadIdx.x;
    int cr = t >> 3, q = t & 7;
    float4 v = *(const float4*)(x + ((size_t)b*CC + c0 + cr)*HW + hw0 + q*4);
    float sf = g_sfac[(s*NB + b)*CC + c0 + cr];
    sm[cr*33 + q*4+0] = v.x*sf;
    sm[cr*33 + q*4+1] = v.y*sf;
    sm[cr*33 + q*4+2] = v.z*sf;
    sm[cr*33 + q*4+3] = v.w*sf;
    __syncthreads();
    float4 o;
    o.x = sm[(q*4+0)*33 + cr];
    o.y = sm[(q*4+1)*33 + cr];
    o.z = sm[(q*4+2)*33 + cr];
    o.w = sm[(q*4+3)*33 + cr];
    *(float4*)(g_xt + ((size_t)b*TP + SOFF + hw0 + cr)*CC + c0 + q*4) = o;
}

// ---------------- 3x3 conv via mma.sync tf32 implicit GEMM -------------------
// 3-way K-split (grid 288, balanced 2 CTAs/SM); double-buffered smem, 1 sync/iter
__global__ __launch_bounds__(256,2) void k_convmma() {
    extern __shared__ float dsm[];

    int tid = threadIdx.x, wid = tid >> 5, lane = tid & 31;
    int x3 = blockIdx.x;
    int third = x3 / 96;
    int x = x3 - third*96;
    int s = (x >= 70) + (x >= 90);
    int r = x - SEL3(s, 0, 70, 90);
    int TILES = SEL3(s, 35, 10, 3);
    int b = r / TILES, tile = r % TILES;
    int H = 64 >> s, W = H, HW = H*W, W2 = W + 2, PPn = (H+2)*(W+2);
    int SOFF = SEL3(s, 0, 4096, 5120);
    int p0 = tile*128;
    const float* xb = g_xt + ((size_t)b*TP + SOFF)*CC;

    int q = tid & 7;
    int pyb[4], pxb[4], rowk[4];
    bool ppok[4];
    int bkk[4], bnq[4];
    bool bok[4];
#pragma unroll
    for (int k = 0; k < 4; k++) {
        rowk[k] = (tid >> 3) + 32*k;
        int pp = p0 + rowk[k];
        ppok[k] = pp < PPn;
        pyb[k] = pp / W2 - 1;
        pxb[k] = pp % W2 - 1;
        int u = tid + 256*k;
        bok[k] = u < 896;
        bkk[k] = u / 28;
        bnq[k] = u % 28;
    }

    float4 rA[4], rB[4];
#define LOADI(i) do {                                                            \
    int _t = (i) >> 3, _ck = (i) & 7;                                            \
    int _dy = _t/3 - 1, _dx = _t%3 - 1;                                          \
    _Pragma("unroll")                                                            \
    for (int k = 0; k < 4; k++) {                                                \
        int _py = pyb[k] + _dy, _px = pxb[k] + _dx;                              \
        bool _v = ppok[k] && (unsigned)_py < (unsigned)H && (unsigned)_px < (unsigned)W; \
        float4 _val = make_float4(0.f, 0.f, 0.f, 0.f);                           \
        if (_v) _val = *(const float4*)(xb + (size_t)(_py*W + _px)*CC + _ck*32 + q*4); \
        rA[k] = _val;                                                            \
        float4 _bv = make_float4(0.f, 0.f, 0.f, 0.f);                            \
        if (bok[k]) _bv = *(const float4*)(g_wt + (size_t)(i)*3584 + bkk[k]*112 + bnq[k]*4); \
        rB[k] = _bv;                                                             \
    }                                                                            \
} while (0)

#define STOREI(st) do {                                                          \
    float* _A = dsm + (st)*CVA;                                                  \
    float* _B = dsm + 2*CVA + (st)*CVB;                                          \
    _Pragma("unroll")                                                            \
    for (int k = 0; k < 4; k++) {                                                \
        float4 v = rA[k];                                                        \
        v.x = tf32r(v.x); v.y = tf32r(v.y); v.z = tf32r(v.z); v.w = tf32r(v.w);  \
        *(float4*)(_A + rowk[k]*36 + q*4) = v;                                   \
        if (bok[k]) *(float4*)(_B + bkk[k]*120 + bnq[k]*4) = rB[k];              \
    }                                                                            \
} while (0)

    float d[2][7][4];
#pragma unroll
    for (int mi = 0; mi < 2; mi++)
#pragma unroll
        for (int ni = 0; ni < 7; ni++)
#pragma unroll
            for (int e = 0; e < 4; e++) d[mi][ni][e] = 0.f;

    int wm = wid & 3, wn = wid >> 2;
    int lr = lane >> 2, kc = lane & 3;

    int i0 = third*24, i1 = i0 + 24;
    LOADI(i0);
    STOREI(0);
    __syncthreads();
    if (i0 + 1 < i1) LOADI(i0 + 1);

    for (int i = i0; i < i1; i++) {
        int cur = (i - i0) & 1;
        const uint32_t* A32 = (const uint32_t*)(dsm + cur*CVA);
        const uint32_t* B32 = (const uint32_t*)(dsm + 2*CVA + cur*CVB);

#pragma unroll
        for (int kq = 0; kq < 32; kq += 8) {
            uint32_t a[2][4];
#pragma unroll
            for (int mi = 0; mi < 2; mi++) {
                int rr = wm*32 + mi*16 + lr;
                a[mi][0] = A32[rr*36 + kq + kc];
                a[mi][1] = A32[(rr+8)*36 + kq + kc];
                a[mi][2] = A32[rr*36 + kq + kc + 4];
                a[mi][3] = A32[(rr+8)*36 + kq + kc + 4];
            }
#pragma unroll
            for (int ni = 0; ni < 7; ni++) {
                int nn = wn*56 + ni*8 + lr;
                uint32_t b0 = B32[(kq+kc)*120 + nn];
                uint32_t b1 = B32[(kq+kc+4)*120 + nn];
                MMA8(d[0][ni], a[0], b0, b1);
                MMA8(d[1][ni], a[1], b0, b1);
            }
        }

        if (i + 1 < i1) {
            STOREI(cur ^ 1);               // safe: all warps done with buf cur^1
            if (i + 2 < i1) LOADI(i + 2);  // prefetch next-next into regs
            __syncthreads();               // publish buf cur^1
        }
    }

    float* obase = g_omp + (size_t)third*POF + OMOFF(s) + (size_t)b*OMC*HW;
#pragma unroll
    for (int mi = 0; mi < 2; mi++) {
#pragma unroll
        for (int h = 0; h < 2; h++) {
            int pp = p0 + wm*32 + mi*16 + lr + h*8;
            int py = pp / W2 - 1, px = pp % W2 - 1;
            bool ok = (pp < PPn) && (unsigned)py < (unsigned)H && (unsigned)px < (unsigned)W;
            if (!ok) continue;
            float* ob = obase + py*W + px;
#pragma unroll
            for (int ni = 0; ni < 7; ni++) {
                int n = wn*56 + ni*8 + 2*kc;
                if (n < OMC)   ob[(size_t)n*HW]     = d[mi][ni][h*2+0];
                if (n+1 < OMC) ob[(size_t)(n+1)*HW] = d[mi][ni][h*2+1];
            }
        }
    }
}

// ---------------- DCN index/weight precompute (sums 3 conv partials + bias) --
__global__ __launch_bounds__(256) void k_dcnidx(const float* __restrict__ bom) {
    int p = blockIdx.x*256 + threadIdx.x;      // 0..5375
    int k = blockIdx.y, bg = blockIdx.z;
    int b = bg >> 2, g = bg & 3;
    int s = (p >= 4096) + (p >= 5120);
    int H = 64 >> s, W = H, HW = H*W;
    int SOFF = SEL3(s, 0, 4096, 5120);
    int hw = p - SOFF;
    int h = hw / W, w = hw % W;
    const float* om0 = g_omp + OMOFF(s) + (size_t)b*OMC*HW;
    const float* om1 = om0 + POF;
    const float* om2 = om1 + POF;
    int ch = (g*9 + k)*3;
    float offy = om0[(size_t)(ch+0)*HW + hw] + om1[(size_t)(ch+0)*HW + hw]
               + om2[(size_t)(ch+0)*HW + hw] + bom[ch+0];
    float offx = om0[(size_t)(ch+1)*HW + hw] + om1[(size_t)(ch+1)*HW + hw]
               + om2[(size_t)(ch+1)*HW + hw] + bom[ch+1];
    float msk  = om0[(size_t)(ch+2)*HW + hw] + om1[(size_t)(ch+2)*HW + hw]
               + om2[(size_t)(ch+2)*HW + hw] + bom[ch+2];
    int ky = k/3 - 1, kx = k%3 - 1;
    float py = (float)(h + ky) + offy;
    float px = (float)(w + kx) + offx;
    float y0f = floorf(py), x0f = floorf(px);
    float fy = py - y0f, fx = px - x0f;
    int y0 = (int)y0f, x0 = (int)x0f;
    size_t ob = ((size_t)(bg*9 + k)*4)*TP + p;
#pragma unroll
    for (int cr = 0; cr < 4; cr++) {
        int dy = cr >> 1, dx = cr & 1;
        int yy = y0 + dy, xx = x0 + dx;
        float wgt = (dy ? fy : 1.f - fy) * (dx ? fx : 1.f - fx);
        bool valid = (yy >= 0) && (yy < H) && (xx >= 0) && (xx < W);
        float weff = valid ? wgt * msk : 0.f;
        int yc = min(max(yy, 0), H-1);
        int xc = min(max(xx, 0), W-1);
        unsigned idxc = (unsigned)(yc*W + xc);
        g_gpk[ob + (size_t)cr*TP] = (ull)idxc | ((ull)__float_as_uint(weff) << 32);
    }
}

// ---------------- DCNv4 pure gather ------------------------------------------
__global__ __launch_bounds__(256) void k_dcn() {
    int bx = blockIdx.x;
    int warp = threadIdx.x >> 5, lane = threadIdx.x & 31;
    int p = bx*8 + warp;                        // global pixel slot
    int s = (p >= 4096) + (p >= 5120);
    int SOFF = SEL3(s, 0, 4096, 5120);
    int g = blockIdx.y, b = blockIdx.z;
    const float* xb = g_xt + ((size_t)b*TP + SOFF)*CC + g*64;
    const ull* pkb = g_gpk + ((size_t)((b*4 + g)*9)*4)*TP + p;
    ull acc = 0ull;
#pragma unroll
    for (int j = 0; j < 36; j++) {
        ull pk = pkb[(size_t)j*TP];
        float wf = __uint_as_float((unsigned)(pk >> 32));
        unsigned idxc = (unsigned)pk;
        const ull* q = (const ull*)(xb + (size_t)idxc*CC);
        f2fma(acc, f2pk(wf, wf), q[lane]);
    }
    ((ull*)(g_dcn + ((size_t)b*TP + p)*CC + g*64))[lane] = acc;
}

// ---------------- 1x1 projection via mma.sync tf32 ---------------------------
__global__ __launch_bounds__(256) void k_projmma(const float* __restrict__ bp) {
    __shared__ float As[128*36];
    __shared__ float Bs[32*152];

    int tid = threadIdx.x, wid = tid >> 5, lane = tid & 31;
    int m0 = blockIdx.x*128, n0 = blockIdx.y*128;

    int q = tid & 7;
    int rowk[4], bkk[4], bnq[4];
#pragma unroll
    for (int k = 0; k < 4; k++) {
        rowk[k] = (tid >> 3) + 32*k;
        int u = tid + 256*k;
        bkk[k] = u >> 5;
        bnq[k] = u & 31;
    }

    float4 rA[4], rB[4];
#define PLOADI(i) do {                                                           \
    int _k0 = (i)*32;                                                            \
    _Pragma("unroll")                                                            \
    for (int k = 0; k < 4; k++) {                                                \
        rA[k] = *(const float4*)(g_dcn + (size_t)(m0 + rowk[k])*CC + _k0 + q*4); \
        rB[k] = *(const float4*)(g_wpj + (size_t)(_k0 + bkk[k])*CC + n0 + bnq[k]*4); \
    }                                                                            \
} while (0)

    float d[2][8][4];
#pragma unroll
    for (int mi = 0; mi < 2; mi++)
#pragma unroll
        for (int ni = 0; ni < 8; ni++)
#pragma unroll
            for (int e = 0; e < 4; e++) d[mi][ni][e] = 0.f;

    int wm = wid & 3, wn = wid >> 2;
    int lr = lane >> 2, kc = lane & 3;
    const uint32_t* A32 = (const uint32_t*)As;
    const uint32_t* B32 = (const uint32_t*)Bs;

    PLOADI(0);
    for (int i = 0; i < 8; i++) {
        if (i > 0) __syncthreads();
#pragma unroll
        for (int k = 0; k < 4; k++) {
            float4 v = rA[k];
            v.x = tf32r(v.x); v.y = tf32r(v.y); v.z = tf32r(v.z); v.w = tf32r(v.w);
            *(float4*)(As + rowk[k]*36 + q*4) = v;
            *(float4*)(Bs + bkk[k]*152 + bnq[k]*4) = rB[k];
        }
        if (i + 1 < 8) PLOADI(i + 1);
        __syncthreads();

#pragma unroll
        for (int kq = 0; kq < 32; kq += 8) {
            uint32_t a[2][4];
#pragma unroll
            for (int mi = 0; mi < 2; mi++) {
                int rr = wm*32 + mi*16 + lr;
                a[mi][0] = A32[rr*36 + kq + kc];
                a[mi][1] = A32[(rr+8)*36 + kq + kc];
                a[mi][2] = A32[rr*36 + kq + kc + 4];
                a[mi][3] = A32[(rr+8)*36 + kq + kc + 4];
            }
#pragma unroll
            for (int ni = 0; ni < 8; ni++) {
                int nn = wn*64 + ni*8 + lr;
                uint32_t b0 = B32[(kq+kc)*152 + nn];
                uint32_t b1 = B32[(kq+kc+4)*152 + nn];
                MMA8(d[0][ni], a[0], b0, b1);
                MMA8(d[1][ni], a[1], b0, b1);
            }
        }
    }

#pragma unroll
    for (int mi = 0; mi < 2; mi++) {
#pragma unroll
        for (int h = 0; h < 2; h++) {
            int m = m0 + wm*32 + mi*16 + lr + h*8;
            float* orow = g_d + (size_t)m*CC;
#pragma unroll
            for (int ni = 0; ni < 8; ni++) {
                int n = n0 + wn*64 + ni*8 + 2*kc;
                float2 v = make_float2(d[mi][ni][h*2+0] + bp[n],
                                       d[mi][ni][h*2+1] + bp[n+1]);
                *(float2*)(orow + n) = v;
            }
        }
    }
}

// ---------------- channel LayerNorm + sigmoid gate (warp per row) ------------
__global__ __launch_bounds__(256) void k_lngate(const float* __restrict__ lng,
                                                const float* __restrict__ lnb) {
    int warp = threadIdx.x >> 5, lane = threadIdx.x & 31;
    int r = blockIdx.x*8 + warp;
    size_t base = (size_t)r*CC;
    float4 v0 = *(const float4*)(g_d + base + lane*8);
    float4 v1 = *(const float4*)(g_d + base + lane*8 + 4);
    float s = v0.x+v0.y+v0.z+v0.w + v1.x+v1.y+v1.z+v1.w;
    float q = v0.x*v0.x+v0.y*v0.y+v0.z*v0.z+v0.w*v0.w
            + v1.x*v1.x+v1.y*v1.y+v1.z*v1.z+v1.w*v1.w;
#pragma unroll
    for (int o = 16; o; o >>= 1) {
        s += __shfl_xor_sync(0xffffffffu, s, o);
        q += __shfl_xor_sync(0xffffffffu, q, o);
    }
    float mu = s * (1.f/CC);
    float rs = rsqrtf(q * (1.f/CC) - mu*mu + 1e-5f);
    float4 g0 = *(const float4*)(lng + lane*8);
    float4 g1 = *(const float4*)(lng + lane*8 + 4);
    float4 b0 = *(const float4*)(lnb + lane*8);
    float4 b1 = *(const float4*)(lnb + lane*8 + 4);
    float4 x0 = *(const float4*)(g_xt + base + lane*8);
    float4 x1 = *(const float4*)(g_xt + base + lane*8 + 4);
    float4 o0, o1;
    o0.x = x0.x / (1.f + expf(-((v0.x-mu)*rs*g0.x + b0.x)));
    o0.y = x0.y / (1.f + expf(-((v0.y-mu)*rs*g0.y + b0.y)));
    o0.z = x0.z / (1.f + expf(-((v0.z-mu)*rs*g0.z + b0.z)));
    o0.w = x0.w / (1.f + expf(-((v0.w-mu)*rs*g0.w + b0.w)));
    o1.x = x1.x / (1.f + expf(-((v1.x-mu)*rs*g1.x + b1.x)));
    o1.y = x1.y / (1.f + expf(-((v1.y-mu)*rs*g1.y + b1.y)));
    o1.z = x1.z / (1.f + expf(-((v1.z-mu)*rs*g1.z + b1.z)));
    o1.w = x1.w / (1.f + expf(-((v1.w-mu)*rs*g1.w + b1.w)));
    *(float4*)(g_x2t + base + lane*8)     = o0;
    *(float4*)(g_x2t + base + lane*8 + 4) = o1;
}

// ---------------- task attention ---------------------------------------------
__global__ __launch_bounds__(256) void k_pool2a() {
    int slab = blockIdx.x, b = blockIdx.y;
    int s = (slab >= 64) + (slab >= 80);
    int sbase = SEL3(s, 0, 64, 80);
    int SOFF = SEL3(s, 0, 4096, 5120);
    int c = threadIdx.x;
    int r0 = SOFF + (slab - sbase)*64;
    float v = 0.f;
    for (int r = r0; r < r0 + 64; r++)
        v += g_x2t[((size_t)b*TP + r)*CC + c];
    g_part[(b*84 + slab)*CC + c] = v;
}

// merged pool2b + task gemv: 6 blocks (sb = s*NB + b)
__global__ __launch_bounds__(256) void k_task(
        const float* __restrict__ wa1, const float* __restrict__ ba1,
        const float* __restrict__ wb1, const float* __restrict__ bb1,
        const float* __restrict__ wa2, const float* __restrict__ ba2,
        const float* __restrict__ wb2, const float* __restrict__ bb2) {
    __shared__ float sp[256];
    int sb = blockIdx.x;
    int s = sb >> 1, b = sb & 1;
    int slabs = SEL3(s, 64, 16, 4);
    int sbase = SEL3(s, 0, 64, 80);
    int HW = 4096 >> (2*s);
    int tid = threadIdx.x;
    float v = 0.f;
    for (int i = 0; i < slabs; i++) v += g_part[(b*84 + sbase + i)*CC + tid];
    sp[tid] = v / (float)HW;
    __syncthreads();
    int wid = tid >> 5, lane = tid & 31;
    for (int u = wid; u < 1024; u += 8) {
        int which = u >> 8, o = u & 255;
        const float* wr = ((which == 0) ? wa1 : (which == 1) ? wb1 :
                           (which == 2) ? wa2 : wb2) + (size_t)o*CC;
        const float* bs = (which == 0) ? ba1 : (which == 1) ? bb1 :
                          (which == 2) ? ba2 : bb2;
        float vv = 0.f;
#pragma unroll
        for (int i = 0; i < 8; i++) vv = fmaf(wr[lane + i*32], sp[lane + i*32], vv);
#pragma unroll
        for (int o2 = 16; o2; o2 >>= 1) vv += __shfl_down_sync(0xffffffffu, vv, o2);
        if (!lane) g_ab[(which*6 + sb)*CC + o] = fmaxf(vv + bs[o], 0.f);
    }
}

// gated output + transpose (vectorized); x-cum {128,160,168}
__global__ __launch_bounds__(256) void k_taskout(float* __restrict__ out) {
    __shared__ float sm[32*33];
    int bx = blockIdx.x;
    int s = (bx >= 128) + (bx >= 160);
    int base = SEL3(s, 0, 128, 160);
    int HW = 4096 >> (2*s);
    int SOFF = SEL3(s, 0, 4096, 5120);
    size_t OOFF = (size_t)NB*CC*SOFF;
    int b = blockIdx.z;
    int hw0 = (bx - base)*32, c0 = blockIdx.y*32;
    int sb = s*NB + b;
    int t = threadIdx.x;
    int hh = t >> 3, q = t & 7;
    float4 v = *(const float4*)(g_x2t + ((size_t)b*TP + SOFF + hw0 + hh)*CC + c0 + q*4);
    float4 A1 = *(const float4*)(g_ab + (size_t)(0*6 + sb)*CC + c0 + q*4);
    float4 B1 = *(const float4*)(g_ab + (size_t)(1*6 + sb)*CC + c0 + q*4);
    float4 A2 = *(const float4*)(g_ab + (size_t)(2*6 + sb)*CC + c0 + q*4);
    float4 B2 = *(const float4*)(g_ab + (size_t)(3*6 + sb)*CC + c0 + q*4);
    sm[(q*4+0)*33 + hh] = fmaxf(fmaf(A1.x, v.x, B1.x), fmaf(A2.x, v.x, B2.x));
    sm[(q*4+1)*33 + hh] = fmaxf(fmaf(A1.y, v.y, B1.y), fmaf(A2.y, v.y, B2.y));
    sm[(q*4+2)*33 + hh] = fmaxf(fmaf(A1.z, v.z, B1.z), fmaf(A2.z, v.z, B2.z));
    sm[(q*4+3)*33 + hh] = fmaxf(fmaf(A1.w, v.w, B1.w), fmaf(A2.w, v.w, B2.w));
    __syncthreads();
    int cr = t >> 3, q2 = t & 7;
    float4 w;
    w.x = sm[cr*33 + q2*4+0];
    w.y = sm[cr*33 + q2*4+1];
    w.z = sm[cr*33 + q2*4+2];
    w.w = sm[cr*33 + q2*4+3];
    *(float4*)(out + OOFF + ((size_t)b*CC + c0 + cr)*HW + hw0 + q2*4) = w;
}

// ---------------- launch ------------------------------------------------------
extern "C" void kernel_launch(void* const* d_in, const int* in_sizes, int n_in,
                              void* d_out, int out_size) {
    const float* f1 = (const float*)d_in[0];
    const float* f2 = (const float*)d_in[1];
    const float* f3 = (const float*)d_in[2];
    const float* w_scale = (const float*)d_in[3];
    const float* b_scale = (const float*)d_in[4];
    const float* w_om    = (const float*)d_in[5];
    const float* b_om    = (const float*)d_in[6];
    const float* w_proj  = (const float*)d_in[7];
    const float* b_proj  = (const float*)d_in[8];
    const float* ln_g    = (const float*)d_in[9];
    const float* ln_b    = (const float*)d_in[10];
    const float* wa1 = (const float*)d_in[11];
    const float* ba1 = (const float*)d_in[12];
    const float* wb1 = (const float*)d_in[13];
    const float* bb1 = (const float*)d_in[14];
    const float* wa2 = (const float*)d_in[15];
    const float* ba2 = (const float*)d_in[16];
    const float* wb2 = (const float*)d_in[17];
    const float* bb2 = (const float*)d_in[18];
    float* out = (float*)d_out;

    cudaFuncSetAttribute(k_convmma, cudaFuncAttributeMaxDynamicSharedMemorySize, CSMEM);

    k_prep<<<2800, 256>>>(w_om, w_proj, f1, f2, f3);
    k_scale_gemv<<<(3*NB*CC*32 + 255)/256, 256>>>(w_scale, b_scale);
    k_apply<<<dim3(168, CC/32, NB), 256>>>(f1, f2, f3);
    k_convmma<<<288, 256, CSMEM>>>();
    k_dcnidx<<<dim3(21, 9, NB*GG), 256>>>(b_om);
    k_dcn<<<dim3(672, GG, NB), 256>>>();
    k_projmma<<<dim3(84, 2), 256>>>(b_proj);
    k_lngate<<<NB*TP/8, 256>>>(ln_g, ln_b);
    k_pool2a<<<dim3(84, NB), 256>>>();
    k_task<<<6, 256>>>(wa1, ba1, wb1, bb1, wa2, ba2, wb2, bb2);
    k_taskout<<<dim3(168, CC/32, NB), 256>>>(out);
}